// round 8
// baseline (speedup 1.0000x reference)
#include <cuda_runtime.h>
#include <math.h>

#define N_PTS 32768
#define H     64
#define NBLK  128
#define TPB   512          // 2 threads per point (k-split), 256 points/block
#define NELEM (N_PTS*3)
#define MAX_STEPS 24

// ---------------- persistent device state (no allocation) ----------------
__device__ volatile int   g_count[MAX_STEPS];
__device__ volatile float g_partials[2][NBLK];

// ---------------- dopri5 tableau ------------------------------------------
__constant__ float cC[7] = { 0.0f, 0.2f, 0.3f, 0.8f, (float)(8.0/9.0), 1.0f, 1.0f };
__constant__ float cA[7][6] = {
    {0,0,0,0,0,0},
    {(float)(1.0/5.0),0,0,0,0,0},
    {(float)(3.0/40.0),(float)(9.0/40.0),0,0,0,0},
    {(float)(44.0/45.0),(float)(-56.0/15.0),(float)(32.0/9.0),0,0,0},
    {(float)(19372.0/6561.0),(float)(-25360.0/2187.0),(float)(64448.0/6561.0),(float)(-212.0/729.0),0,0},
    {(float)(9017.0/3168.0),(float)(-355.0/33.0),(float)(46732.0/5247.0),(float)(49.0/176.0),(float)(-5103.0/18656.0),0},
    {(float)(35.0/384.0),0.0f,(float)(500.0/1113.0),(float)(125.0/192.0),(float)(-2187.0/6784.0),(float)(11.0/84.0)},
};
__constant__ float cB[7] = {
    (float)(35.0/384.0), 0.0f, (float)(500.0/1113.0), (float)(125.0/192.0),
    (float)(-2187.0/6784.0), (float)(11.0/84.0), 0.0f
};
__constant__ float cE[7] = {
    (float)(35.0/384.0 - 5179.0/57600.0),
    0.0f,
    (float)(500.0/1113.0 - 7571.0/16695.0),
    (float)(125.0/192.0 - 393.0/640.0),
    (float)(-2187.0/6784.0 + 92097.0/339200.0),
    (float)(11.0/84.0 - 187.0/2100.0),
    (float)(-1.0/40.0)
};

// ---------------- packed f32x2 helpers (Blackwell) ------------------------
__device__ __forceinline__ unsigned long long ffma2(unsigned long long a,
                                                    unsigned long long b,
                                                    unsigned long long c)
{
    unsigned long long d;
    asm("fma.rn.f32x2 %0, %1, %2, %3;" : "=l"(d) : "l"(a), "l"(b), "l"(c));
    return d;
}
__device__ __forceinline__ unsigned long long add2(unsigned long long a,
                                                   unsigned long long b)
{
    unsigned long long d;
    asm("add.rn.f32x2 %0, %1, %2;" : "=l"(d) : "l"(a), "l"(b));
    return d;
}
__device__ __forceinline__ unsigned long long splat2(float x)
{
    unsigned long long d;
    asm("mov.b64 %0, {%1, %1};" : "=l"(d) : "f"(x));
    return d;
}
__device__ __forceinline__ void unpack2(unsigned long long v, float& lo, float& hi)
{
    asm("mov.b64 {%0, %1}, %2;" : "=f"(lo), "=f"(hi) : "l"(v));
}

// ---------------- fast tanh: ex2.approx + rcp.approx + 1 Newton ----------
__device__ __forceinline__ float fast_tanh(float x)
{
    x = fminf(fmaxf(x, -9.0f), 9.0f);
    float e;
    asm("ex2.approx.f32 %0, %1;" : "=f"(e) : "f"(x * 2.8853900817779268f)); // 2*log2(e)
    float d = e + 1.0f;
    float r;
    asm("rcp.approx.f32 %0, %1;" : "=f"(r) : "f"(d));
    r = r * fmaf(-d, r, 2.0f);
    return fmaf(-2.0f, r, 1.0f);
}

// ---------------- MLP eval, k-split across a lane pair --------------------
// sub=tid&1. This thread processes k in [sub*32, sub*32+32): computes those
// 32 layer-1 neurons on the fly and accumulates their rank-1 updates into
// partial sums for ALL 64 layer-2 neurons (32 packed accs). One batched
// exchange combines partials; each lane finishes 32 neurons of layer 2/3.
// Returns the full output f, bitwise identical on both lanes.
__device__ __forceinline__ float3 mlp_eval_ksplit(
    const float4* __restrict__ sW1t, const float* __restrict__ sb1,
    const float*  __restrict__ sW2,  const float* __restrict__ sb2,
    const float4* __restrict__ sW3,  const float* __restrict__ sb3,
    int sub, int lane,
    float t, float x0, float x1, float x2)
{
    const int kbase = sub * (H / 2);

    unsigned long long acc[H / 2];   // partial sums, all 64 neurons (32 pairs)
    if (sub == 0) {                  // bias counted exactly once (even lane)
        const unsigned long long* b2p = (const unsigned long long*)sb2;
#pragma unroll
        for (int p = 0; p < H / 2; p++) acc[p] = b2p[p];
    } else {
#pragma unroll
        for (int p = 0; p < H / 2; p++) acc[p] = 0ULL;
    }

#pragma unroll 4
    for (int k = 0; k < H / 2; k++) {
        const int kk = kbase + k;
        // layer-1 neuron kk on the fly
        float4 w = sW1t[kk];
        float a = fmaf(t, w.w, sb1[kk]);
        a = fmaf(x2, w.z, a);
        a = fmaf(x1, w.y, a);
        a = fmaf(x0, w.x, a);
        unsigned long long hs = splat2(fast_tanh(a));

        // rank-1 update into all 64 neurons
        const ulonglong2* wrow = (const ulonglong2*)(sW2 + kk * H);
#pragma unroll
        for (int q = 0; q < H / 4; q++) {
            ulonglong2 wv = wrow[q];
            acc[2 * q]     = ffma2(hs, wv.x, acc[2 * q]);
            acc[2 * q + 1] = ffma2(hs, wv.y, acc[2 * q + 1]);
        }
    }

    // ---- batched pair exchange: each lane keeps its 16 pairs ----
    // even lane finishes neuron pairs 0..15, odd lane pairs 16..31.
    // even sends acc[16+p] (odd needs it), receives odd's acc[p]; vice versa.
    unsigned long long mine[H / 4];
#pragma unroll
    for (int p = 0; p < H / 4; p++) {
        unsigned long long send = (sub == 0) ? acc[(H / 4) + p] : acc[p];
        unsigned long long recv = __shfl_xor_sync(0xFFFFFFFFu, send, 1);
        unsigned long long keep = (sub == 0) ? acc[p] : acc[(H / 4) + p];
        mine[p] = add2(keep, recv);
    }

    // ---- tanh + layer-3 partial over my 32 neurons ----
    const int nbase = sub * (H / 2);
    float o0 = 0.0f, o1 = 0.0f, o2 = 0.0f;
#pragma unroll
    for (int p = 0; p < H / 4; p++) {
        float u, v;
        unpack2(mine[p], u, v);
        float ha = fast_tanh(u);
        float hb = fast_tanh(v);
        float4 wa = sW3[nbase + 2 * p];
        float4 wb = sW3[nbase + 2 * p + 1];
        o0 = fmaf(ha, wa.x, o0); o1 = fmaf(ha, wa.y, o1); o2 = fmaf(ha, wa.z, o2);
        o0 = fmaf(hb, wb.x, o0); o1 = fmaf(hb, wb.y, o1); o2 = fmaf(hb, wb.z, o2);
    }
    // fixed-order combine (even + odd) -> bitwise identical on both lanes
    const int pair_even = lane & ~1;
    float e0 = __shfl_sync(0xFFFFFFFFu, o0, pair_even);
    float e1 = __shfl_sync(0xFFFFFFFFu, o1, pair_even);
    float e2 = __shfl_sync(0xFFFFFFFFu, o2, pair_even);
    float d0 = __shfl_sync(0xFFFFFFFFu, o0, pair_even + 1);
    float d1 = __shfl_sync(0xFFFFFFFFu, o1, pair_even + 1);
    float d2 = __shfl_sync(0xFFFFFFFFu, o2, pair_even + 1);
    return make_float3(sb3[0] + e0 + d0, sb3[1] + e1 + d1, sb3[2] + e2 + d2);
}

// ---------------- init: reset barrier counters every replay ---------------
__global__ void ode_init_kernel()
{
    int i = threadIdx.x;
    if (i < MAX_STEPS) g_count[i] = 0;
}

// ---------------- persistent fused integrator -----------------------------
__global__ void __launch_bounds__(TPB, 1)
ode_persistent_kernel(const float* __restrict__ yin,
                      const float* __restrict__ W1, const float* __restrict__ b1,
                      const float* __restrict__ W2, const float* __restrict__ b2,
                      const float* __restrict__ W3, const float* __restrict__ b3,
                      float* __restrict__ yout)
{
    __shared__ __align__(16) float4 sW1t[H];
    __shared__ __align__(16) float  sb1[H];
    __shared__ __align__(16) float  sW2[H * H];    // natural [k][j] layout
    __shared__ __align__(16) float  sb2[H];
    __shared__ __align__(16) float4 sW3[H];
    __shared__ __align__(16) float  sb3[4];
    __shared__ float  red[TPB];

    const int tid  = threadIdx.x;
    const int bid  = blockIdx.x;
    const int lane = tid & 31;
    const int sub  = tid & 1;

    {
        const float4* src = (const float4*)W2;
        float4* dst = (float4*)sW2;
        for (int idx = tid; idx < H * H / 4; idx += TPB) dst[idx] = src[idx];
    }
    if (tid < H) {
        sW1t[tid] = make_float4(W1[0*H + tid], W1[1*H + tid], W1[2*H + tid], W1[3*H + tid]);
        sb1[tid] = b1[tid];
        sb2[tid] = b2[tid];
        sW3[tid] = make_float4(W3[tid*3 + 0], W3[tid*3 + 1], W3[tid*3 + 2], 0.0f);
    }
    if (tid < 3) sb3[tid] = b3[tid];
    __syncthreads();

    const int n = bid * (TPB / 2) + (tid >> 1);    // point index (pair-shared)
    float y0 = yin[3*n + 0];
    float y1 = yin[3*n + 1];
    float y2 = yin[3*n + 2];

    float t  = 0.0f;
    float dt = 0.05f;

    for (int s = 0; s < MAX_STEPS; s++) {
        const float rem = 1.0f - t;
        if (!(rem > 1e-9f)) break;                 // identical across all threads
        const float dtc = fminf(dt, rem);

        // ---- 7 dopri5 stages (state replicated in both lanes of the pair) ----
        float kb[7][3];
#pragma unroll 1
        for (int i = 0; i < 7; i++) {
            float yi0 = y0, yi1 = y1, yi2 = y2;
            for (int j = 0; j < i; j++) {
                float c = dtc * cA[i][j];
                yi0 += c * kb[j][0];
                yi1 += c * kb[j][1];
                yi2 += c * kb[j][2];
            }
            float3 f = mlp_eval_ksplit(sW1t, sb1, sW2, sb2, sW3, sb3,
                                       sub, lane, t + cC[i] * dtc, yi0, yi1, yi2);
            kb[i][0] = f.x; kb[i][1] = f.y; kb[i][2] = f.z;
        }

        float yn0 = y0, yn1 = y1, yn2 = y2;
        float ye0 = 0.0f, ye1 = 0.0f, ye2 = 0.0f;
        for (int i = 0; i < 7; i++) {
            float cb = dtc * cB[i];
            float ce = dtc * cE[i];
            yn0 += cb * kb[i][0]; yn1 += cb * kb[i][1]; yn2 += cb * kb[i][2];
            ye0 += ce * kb[i][0]; ye1 += ce * kb[i][1]; ye2 += ce * kb[i][2];
        }

        // ---- per-point error (counted once: even lane) ----
        float local = 0.0f;
        if (sub == 0) {
            float tol0 = 1e-5f + 1e-5f * fmaxf(fabsf(y0), fabsf(yn0));
            float tol1 = 1e-5f + 1e-5f * fmaxf(fabsf(y1), fabsf(yn1));
            float tol2 = 1e-5f + 1e-5f * fmaxf(fabsf(y2), fabsf(yn2));
            float r0 = ye0 / tol0, r1 = ye1 / tol1, r2 = ye2 / tol2;
            local = r0*r0 + (r1*r1 + r2*r2);
        }
        red[tid] = local;
        __syncthreads();
        for (int sh = TPB / 2; sh > 0; sh >>= 1) {
            if (tid < sh) red[tid] += red[tid + sh];
            __syncthreads();
        }

        // ---- grid barrier: publish partial, arrive, spin ----
        const int buf = s & 1;
        if (tid == 0) {
            g_partials[buf][bid] = red[0];
            __threadfence();
            atomicAdd((int*)&g_count[s], 1);
            while (g_count[s] < NBLK) { }
            __threadfence();
        }
        __syncthreads();

        // ---- redundant, deterministic controller in every block ----
        if (tid < NBLK) red[tid] = g_partials[buf][tid];
        __syncthreads();
        for (int sh = NBLK / 2; sh > 0; sh >>= 1) {
            if (tid < sh) red[tid] += red[tid + sh];
            __syncthreads();
        }
        float total = red[0];
        __syncthreads();

        float err = sqrtf(total / (float)NELEM);
        err = fmaxf(err, 1e-10f);
        bool accept = err <= 1.0f;
        float factor = 0.9f * powf(err, -0.2f);
        factor = fminf(fmaxf(factor, 0.2f), 10.0f);
        if (accept) { t += dtc; y0 = yn0; y1 = yn1; y2 = yn2; }
        dt = dtc * factor;
    }

    if (sub == 0) {
        yout[3*n + 0] = y0;
        yout[3*n + 1] = y1;
        yout[3*n + 2] = y2;
    }
}

// ---------------- launch --------------------------------------------------
extern "C" void kernel_launch(void* const* d_in, const int* in_sizes, int n_in,
                              void* d_out, int out_size)
{
    const float* y_in = (const float*)d_in[0];
    const float* W1   = (const float*)d_in[1];
    const float* b1   = (const float*)d_in[2];
    const float* W2   = (const float*)d_in[3];
    const float* b2   = (const float*)d_in[4];
    const float* W3   = (const float*)d_in[5];
    const float* b3   = (const float*)d_in[6];
    float* y = (float*)d_out;

    ode_init_kernel<<<1, 32>>>();
    ode_persistent_kernel<<<NBLK, TPB>>>(y_in, W1, b1, W2, b2, W3, b3, y);
}

// round 9
// speedup vs baseline: 1.1713x; 1.1713x over previous
#include <cuda_runtime.h>
#include <math.h>

#define N_PTS 32768
#define H     64
#define NBLK  128
#define TPB   512          // 2 threads/point (neuron-split), 256 points/block
#define NELEM (N_PTS*3)
#define MAX_STEPS 24

// padded W2 row: 64 floats stored as [0:32) at word 0, [32:64) at word 36.
// 72 words/row -> lane-half addresses never share a bank (offset 4 banks).
#define ROWW     72
#define HALF_OFF 36

// ---------------- persistent device state (no allocation) ----------------
__device__ volatile int   g_count[MAX_STEPS];
__device__ volatile float g_partials[2][NBLK];

// ---------------- dopri5 tableau ------------------------------------------
__constant__ float cC[7] = { 0.0f, 0.2f, 0.3f, 0.8f, (float)(8.0/9.0), 1.0f, 1.0f };
__constant__ float cA[7][6] = {
    {0,0,0,0,0,0},
    {(float)(1.0/5.0),0,0,0,0,0},
    {(float)(3.0/40.0),(float)(9.0/40.0),0,0,0,0},
    {(float)(44.0/45.0),(float)(-56.0/15.0),(float)(32.0/9.0),0,0,0},
    {(float)(19372.0/6561.0),(float)(-25360.0/2187.0),(float)(64448.0/6561.0),(float)(-212.0/729.0),0,0},
    {(float)(9017.0/3168.0),(float)(-355.0/33.0),(float)(46732.0/5247.0),(float)(49.0/176.0),(float)(-5103.0/18656.0),0},
    {(float)(35.0/384.0),0.0f,(float)(500.0/1113.0),(float)(125.0/192.0),(float)(-2187.0/6784.0),(float)(11.0/84.0)},
};
__constant__ float cB[7] = {
    (float)(35.0/384.0), 0.0f, (float)(500.0/1113.0), (float)(125.0/192.0),
    (float)(-2187.0/6784.0), (float)(11.0/84.0), 0.0f
};
__constant__ float cE[7] = {
    (float)(35.0/384.0 - 5179.0/57600.0),
    0.0f,
    (float)(500.0/1113.0 - 7571.0/16695.0),
    (float)(125.0/192.0 - 393.0/640.0),
    (float)(-2187.0/6784.0 + 92097.0/339200.0),
    (float)(11.0/84.0 - 187.0/2100.0),
    (float)(-1.0/40.0)
};

// ---------------- packed f32x2 helpers (Blackwell) ------------------------
__device__ __forceinline__ unsigned long long ffma2(unsigned long long a,
                                                    unsigned long long b,
                                                    unsigned long long c)
{
    unsigned long long d;
    asm("fma.rn.f32x2 %0, %1, %2, %3;" : "=l"(d) : "l"(a), "l"(b), "l"(c));
    return d;
}
__device__ __forceinline__ unsigned long long splat2(float x)
{
    unsigned long long d;
    asm("mov.b64 %0, {%1, %1};" : "=l"(d) : "f"(x));
    return d;
}
__device__ __forceinline__ void unpack2(unsigned long long v, float& lo, float& hi)
{
    asm("mov.b64 {%0, %1}, %2;" : "=f"(lo), "=f"(hi) : "l"(v));
}

// ---------------- fast tanh: ex2.approx + rcp.approx + 1 Newton ----------
__device__ __forceinline__ float fast_tanh(float x)
{
    x = fminf(fmaxf(x, -9.0f), 9.0f);
    float e;
    asm("ex2.approx.f32 %0, %1;" : "=f"(e) : "f"(x * 2.8853900817779268f)); // 2*log2(e)
    float d = e + 1.0f;
    float r;
    asm("rcp.approx.f32 %0, %1;" : "=f"(r) : "f"(d));
    r = r * fmaf(-d, r, 2.0f);
    return fmaf(-2.0f, r, 1.0f);
}

// ---------------- MLP eval, neuron-split across a lane pair ---------------
// sub=tid&1. This thread owns layer-2/3 neurons [sub*32, sub*32+32).
// Both lanes run all 64 k (layer-1 duplicated). All inner-loop LDS are
// single-wavefront: layer-1 is a true broadcast; layer-2's two half-row
// addresses are bank-disjoint thanks to the 288-byte padded rows.
__device__ __forceinline__ float3 mlp_eval_nsplit(
    const float4* __restrict__ sW1t, const float* __restrict__ sb1,
    const float*  __restrict__ sW2p, const float* __restrict__ sb2,
    const float4* __restrict__ sW3,  const float* __restrict__ sb3,
    int sub, int lane,
    float t, float x0, float x1, float x2)
{
    const int nbase = sub * (H / 2);

    unsigned long long acc[H / 4];            // 16 pairs = my 32 neurons
    {
        const unsigned long long* b2p = (const unsigned long long*)(sb2 + nbase);
#pragma unroll
        for (int p = 0; p < H / 4; p++) acc[p] = b2p[p];
    }

    const int half_w = sub * HALF_OFF;        // word offset of my half-row
#pragma unroll 4
    for (int k = 0; k < H; k++) {
        // layer-1 neuron k on the fly (identical in both lanes, broadcast LDS)
        float4 w = sW1t[k];
        float a = fmaf(t, w.w, sb1[k]);
        a = fmaf(x2, w.z, a);
        a = fmaf(x1, w.y, a);
        a = fmaf(x0, w.x, a);
        unsigned long long hs = splat2(fast_tanh(a));

        // rank-1 update into my 32 neurons (8 x 16B, bank-disjoint per pair)
        const ulonglong2* wrow = (const ulonglong2*)(sW2p + k * ROWW + half_w);
#pragma unroll
        for (int q = 0; q < H / 8; q++) {
            ulonglong2 wv = wrow[q];
            acc[2 * q]     = ffma2(hs, wv.x, acc[2 * q]);
            acc[2 * q + 1] = ffma2(hs, wv.y, acc[2 * q + 1]);
        }
    }

    // ---- tanh + layer-3 partial over my 32 neurons ----
    float o0 = 0.0f, o1 = 0.0f, o2 = 0.0f;
#pragma unroll
    for (int p = 0; p < H / 4; p++) {
        float u, v;
        unpack2(acc[p], u, v);
        float ha = fast_tanh(u);
        float hb = fast_tanh(v);
        float4 wa = sW3[nbase + 2 * p];
        float4 wb = sW3[nbase + 2 * p + 1];
        o0 = fmaf(ha, wa.x, o0); o1 = fmaf(ha, wa.y, o1); o2 = fmaf(ha, wa.z, o2);
        o0 = fmaf(hb, wb.x, o0); o1 = fmaf(hb, wb.y, o1); o2 = fmaf(hb, wb.z, o2);
    }
    // fixed-order combine (even + odd) -> bitwise identical on both lanes
    const int pair_even = lane & ~1;
    float e0 = __shfl_sync(0xFFFFFFFFu, o0, pair_even);
    float e1 = __shfl_sync(0xFFFFFFFFu, o1, pair_even);
    float e2 = __shfl_sync(0xFFFFFFFFu, o2, pair_even);
    float d0 = __shfl_sync(0xFFFFFFFFu, o0, pair_even + 1);
    float d1 = __shfl_sync(0xFFFFFFFFu, o1, pair_even + 1);
    float d2 = __shfl_sync(0xFFFFFFFFu, o2, pair_even + 1);
    return make_float3(sb3[0] + e0 + d0, sb3[1] + e1 + d1, sb3[2] + e2 + d2);
}

// ---------------- init: reset barrier counters every replay ---------------
__global__ void ode_init_kernel()
{
    int i = threadIdx.x;
    if (i < MAX_STEPS) g_count[i] = 0;
}

// ---------------- persistent fused integrator -----------------------------
__global__ void __launch_bounds__(TPB, 1)
ode_persistent_kernel(const float* __restrict__ yin,
                      const float* __restrict__ W1, const float* __restrict__ b1,
                      const float* __restrict__ W2, const float* __restrict__ b2,
                      const float* __restrict__ W3, const float* __restrict__ b3,
                      float* __restrict__ yout)
{
    __shared__ __align__(16) float4 sW1t[H];
    __shared__ __align__(16) float  sb1[H];
    __shared__ __align__(16) float  sW2p[H * ROWW];   // padded rows
    __shared__ __align__(16) float  sb2[H];
    __shared__ __align__(16) float4 sW3[H];
    __shared__ __align__(16) float  sb3[4];
    __shared__ float  red[TPB];

    const int tid  = threadIdx.x;
    const int bid  = blockIdx.x;
    const int lane = tid & 31;
    const int sub  = tid & 1;

    // W2 copy into padded layout
    for (int idx = tid; idx < H * H; idx += TPB) {
        int row = idx >> 6, col = idx & 63;
        int woff = row * ROWW + ((col < 32) ? col : (HALF_OFF + col - 32));
        sW2p[woff] = W2[idx];
    }
    if (tid < H) {
        sW1t[tid] = make_float4(W1[0*H + tid], W1[1*H + tid], W1[2*H + tid], W1[3*H + tid]);
        sb1[tid] = b1[tid];
        sb2[tid] = b2[tid];
        sW3[tid] = make_float4(W3[tid*3 + 0], W3[tid*3 + 1], W3[tid*3 + 2], 0.0f);
    }
    if (tid < 3) sb3[tid] = b3[tid];
    __syncthreads();

    const int n = bid * (TPB / 2) + (tid >> 1);    // point index (pair-shared)
    float y0 = yin[3*n + 0];
    float y1 = yin[3*n + 1];
    float y2 = yin[3*n + 2];

    float t  = 0.0f;
    float dt = 0.05f;

    for (int s = 0; s < MAX_STEPS; s++) {
        const float rem = 1.0f - t;
        if (!(rem > 1e-9f)) break;                 // identical across all threads
        const float dtc = fminf(dt, rem);

        // ---- 7 dopri5 stages (state replicated in both lanes of the pair) ----
        float kb[7][3];
#pragma unroll 1
        for (int i = 0; i < 7; i++) {
            float yi0 = y0, yi1 = y1, yi2 = y2;
            for (int j = 0; j < i; j++) {
                float c = dtc * cA[i][j];
                yi0 += c * kb[j][0];
                yi1 += c * kb[j][1];
                yi2 += c * kb[j][2];
            }
            float3 f = mlp_eval_nsplit(sW1t, sb1, sW2p, sb2, sW3, sb3,
                                       sub, lane, t + cC[i] * dtc, yi0, yi1, yi2);
            kb[i][0] = f.x; kb[i][1] = f.y; kb[i][2] = f.z;
        }

        float yn0 = y0, yn1 = y1, yn2 = y2;
        float ye0 = 0.0f, ye1 = 0.0f, ye2 = 0.0f;
        for (int i = 0; i < 7; i++) {
            float cb = dtc * cB[i];
            float ce = dtc * cE[i];
            yn0 += cb * kb[i][0]; yn1 += cb * kb[i][1]; yn2 += cb * kb[i][2];
            ye0 += ce * kb[i][0]; ye1 += ce * kb[i][1]; ye2 += ce * kb[i][2];
        }

        // ---- per-point error (counted once: even lane) ----
        float local = 0.0f;
        if (sub == 0) {
            float tol0 = 1e-5f + 1e-5f * fmaxf(fabsf(y0), fabsf(yn0));
            float tol1 = 1e-5f + 1e-5f * fmaxf(fabsf(y1), fabsf(yn1));
            float tol2 = 1e-5f + 1e-5f * fmaxf(fabsf(y2), fabsf(yn2));
            float r0 = ye0 / tol0, r1 = ye1 / tol1, r2 = ye2 / tol2;
            local = r0*r0 + (r1*r1 + r2*r2);
        }
        red[tid] = local;
        __syncthreads();
        for (int sh = TPB / 2; sh > 0; sh >>= 1) {
            if (tid < sh) red[tid] += red[tid + sh];
            __syncthreads();
        }

        // ---- grid barrier: publish partial, arrive, spin ----
        const int buf = s & 1;
        if (tid == 0) {
            g_partials[buf][bid] = red[0];
            __threadfence();
            atomicAdd((int*)&g_count[s], 1);
            while (g_count[s] < NBLK) { }
            __threadfence();
        }
        __syncthreads();

        // ---- redundant, deterministic controller in every block ----
        if (tid < NBLK) red[tid] = g_partials[buf][tid];
        __syncthreads();
        for (int sh = NBLK / 2; sh > 0; sh >>= 1) {
            if (tid < sh) red[tid] += red[tid + sh];
            __syncthreads();
        }
        float total = red[0];
        __syncthreads();

        float err = sqrtf(total / (float)NELEM);
        err = fmaxf(err, 1e-10f);
        bool accept = err <= 1.0f;
        float factor = 0.9f * powf(err, -0.2f);
        factor = fminf(fmaxf(factor, 0.2f), 10.0f);
        if (accept) { t += dtc; y0 = yn0; y1 = yn1; y2 = yn2; }
        dt = dtc * factor;
    }

    if (sub == 0) {
        yout[3*n + 0] = y0;
        yout[3*n + 1] = y1;
        yout[3*n + 2] = y2;
    }
}

// ---------------- launch --------------------------------------------------
extern "C" void kernel_launch(void* const* d_in, const int* in_sizes, int n_in,
                              void* d_out, int out_size)
{
    const float* y_in = (const float*)d_in[0];
    const float* W1   = (const float*)d_in[1];
    const float* b1   = (const float*)d_in[2];
    const float* W2   = (const float*)d_in[3];
    const float* b2   = (const float*)d_in[4];
    const float* W3   = (const float*)d_in[5];
    const float* b3   = (const float*)d_in[6];
    float* y = (float*)d_out;

    ode_init_kernel<<<1, 32>>>();
    ode_persistent_kernel<<<NBLK, TPB>>>(y_in, W1, b1, W2, b2, W3, b3, y);
}

// round 10
// speedup vs baseline: 1.7876x; 1.5262x over previous
#include <cuda_runtime.h>
#include <math.h>

#define N_PTS 32768
#define H     64
#define NBLK  128
#define TPB   256
#define NELEM (N_PTS*3)
#define MAX_STEPS 24
#define NWARP (TPB/32)

// ---------------- persistent device state (no allocation) ----------------
__device__ volatile int   g_count[MAX_STEPS];
__device__ volatile float g_partials[2][NBLK];

// ---------------- dopri5 tableau ------------------------------------------
__constant__ float cC[7] = { 0.0f, 0.2f, 0.3f, 0.8f, (float)(8.0/9.0), 1.0f, 1.0f };
__constant__ float cA[7][6] = {
    {0,0,0,0,0,0},
    {(float)(1.0/5.0),0,0,0,0,0},
    {(float)(3.0/40.0),(float)(9.0/40.0),0,0,0,0},
    {(float)(44.0/45.0),(float)(-56.0/15.0),(float)(32.0/9.0),0,0,0},
    {(float)(19372.0/6561.0),(float)(-25360.0/2187.0),(float)(64448.0/6561.0),(float)(-212.0/729.0),0,0},
    {(float)(9017.0/3168.0),(float)(-355.0/33.0),(float)(46732.0/5247.0),(float)(49.0/176.0),(float)(-5103.0/18656.0),0},
    {(float)(35.0/384.0),0.0f,(float)(500.0/1113.0),(float)(125.0/192.0),(float)(-2187.0/6784.0),(float)(11.0/84.0)},
};
__constant__ float cB[7] = {
    (float)(35.0/384.0), 0.0f, (float)(500.0/1113.0), (float)(125.0/192.0),
    (float)(-2187.0/6784.0), (float)(11.0/84.0), 0.0f
};
__constant__ float cE[7] = {
    (float)(35.0/384.0 - 5179.0/57600.0),
    0.0f,
    (float)(500.0/1113.0 - 7571.0/16695.0),
    (float)(125.0/192.0 - 393.0/640.0),
    (float)(-2187.0/6784.0 + 92097.0/339200.0),
    (float)(11.0/84.0 - 187.0/2100.0),
    (float)(-1.0/40.0)
};

// ---------------- packed f32x2 helpers (Blackwell FFMA2) ------------------
__device__ __forceinline__ unsigned long long ffma2(unsigned long long a,
                                                    unsigned long long b,
                                                    unsigned long long c)
{
    unsigned long long d;
    asm("fma.rn.f32x2 %0, %1, %2, %3;" : "=l"(d) : "l"(a), "l"(b), "l"(c));
    return d;
}
__device__ __forceinline__ unsigned long long splat2(float x)
{
    unsigned long long d;
    asm("mov.b64 %0, {%1, %1};" : "=l"(d) : "f"(x));
    return d;
}
__device__ __forceinline__ void unpack2(unsigned long long v, float& lo, float& hi)
{
    asm("mov.b64 {%0, %1}, %2;" : "=f"(lo), "=f"(hi) : "l"(v));
}

// ---------------- fast tanh: ex2.approx + rcp.approx + 1 Newton ----------
__device__ __forceinline__ float fast_tanh(float x)
{
    x = fminf(fmaxf(x, -9.0f), 9.0f);
    float e;
    asm("ex2.approx.f32 %0, %1;" : "=f"(e) : "f"(x * 2.8853900817779268f)); // 2*log2(e)
    float d = e + 1.0f;
    float r;
    asm("rcp.approx.f32 %0, %1;" : "=f"(r) : "f"(d));
    r = r * fmaf(-d, r, 2.0f);
    return fmaf(-2.0f, r, 1.0f);
}

// ---------------- MLP: x(3)+t -> tanh(64) -> tanh(64) -> 3 ---------------
// Layer 1 fused into the layer-2 k-loop; 32 packed f32x2 accumulators.
__device__ __forceinline__ float3 mlp_eval(
    const float4* __restrict__ sW1t, const float* __restrict__ sb1,
    const float*  __restrict__ sW2,  const float* __restrict__ sb2,
    const float4* __restrict__ sW3,  const float* __restrict__ sb3,
    float t, float x0, float x1, float x2)
{
    unsigned long long acc[H / 2];          // 32 packed pairs = 64 neurons
    {
        const unsigned long long* b2p = (const unsigned long long*)sb2;
#pragma unroll
        for (int p = 0; p < H / 2; p++) acc[p] = b2p[p];
    }

#pragma unroll 4
    for (int k = 0; k < H; k++) {
        float4 w = sW1t[k];
        float a = fmaf(t, w.w, sb1[k]);
        a = fmaf(x2, w.z, a);
        a = fmaf(x1, w.y, a);
        a = fmaf(x0, w.x, a);
        unsigned long long hs = splat2(fast_tanh(a));

        const ulonglong2* wrow = (const ulonglong2*)(sW2 + k * H);
#pragma unroll
        for (int q = 0; q < H / 4; q++) {     // full 64-float row
            ulonglong2 wv = wrow[q];
            acc[2 * q]     = ffma2(hs, wv.x, acc[2 * q]);
            acc[2 * q + 1] = ffma2(hs, wv.y, acc[2 * q + 1]);
        }
    }

    float o0 = sb3[0], o1 = sb3[1], o2 = sb3[2];
#pragma unroll
    for (int p = 0; p < H / 2; p++) {
        float u, v;
        unpack2(acc[p], u, v);
        float ha = fast_tanh(u);
        float hb = fast_tanh(v);
        float4 wa = sW3[2 * p];
        float4 wb = sW3[2 * p + 1];
        o0 = fmaf(ha, wa.x, o0); o1 = fmaf(ha, wa.y, o1); o2 = fmaf(ha, wa.z, o2);
        o0 = fmaf(hb, wb.x, o0); o1 = fmaf(hb, wb.y, o1); o2 = fmaf(hb, wb.z, o2);
    }
    return make_float3(o0, o1, o2);
}

// ---------------- init: reset barrier counters every replay ---------------
__global__ void ode_init_kernel()
{
    int i = threadIdx.x;
    if (i < MAX_STEPS) g_count[i] = 0;
}

// ---------------- persistent fused integrator (FSAL) ----------------------
__global__ void __launch_bounds__(TPB, 1)
ode_persistent_kernel(const float* __restrict__ yin,
                      const float* __restrict__ W1, const float* __restrict__ b1,
                      const float* __restrict__ W2, const float* __restrict__ b2,
                      const float* __restrict__ W3, const float* __restrict__ b3,
                      float* __restrict__ yout)
{
    __shared__ __align__(16) float4 sW1t[H];
    __shared__ __align__(16) float  sb1[H];
    __shared__ __align__(16) float  sW2[H * H];    // natural [k][j] layout
    __shared__ __align__(16) float  sb2[H];
    __shared__ __align__(16) float4 sW3[H];
    __shared__ __align__(16) float  sb3[4];
    __shared__ float  rwarp[NWARP];                // per-warp partials
    __shared__ float  rctrl[4];                    // controller cross-warp partials

    const int tid  = threadIdx.x;
    const int bid  = blockIdx.x;
    const int lane = tid & 31;
    const int wid  = tid >> 5;

    {
        const float4* src = (const float4*)W2;
        float4* dst = (float4*)sW2;
        for (int idx = tid; idx < H * H / 4; idx += TPB) dst[idx] = src[idx];
    }
    if (tid < H) {
        sW1t[tid] = make_float4(W1[0*H + tid], W1[1*H + tid], W1[2*H + tid], W1[3*H + tid]);
        sb1[tid] = b1[tid];
        sb2[tid] = b2[tid];
        sW3[tid] = make_float4(W3[tid*3 + 0], W3[tid*3 + 1], W3[tid*3 + 2], 0.0f);
    }
    if (tid < 3) sb3[tid] = b3[tid];
    __syncthreads();

    const int n = bid * TPB + tid;
    float y0 = yin[3*n + 0];
    float y1 = yin[3*n + 1];
    float y2 = yin[3*n + 2];

    float t  = 0.0f;
    float dt = 0.05f;

    // FSAL cache: k1 at current (t, y). Valid after the first step.
    float k1c0 = 0.0f, k1c1 = 0.0f, k1c2 = 0.0f;
    bool  have_k1 = false;

    for (int s = 0; s < MAX_STEPS; s++) {
        const float rem = 1.0f - t;
        if (!(rem > 1e-9f)) break;                 // identical across blocks
        const float dtc = fminf(dt, rem);

        // ---- 7 dopri5 stages (stage 0 from FSAL cache when available) ----
        float kb[7][3];
#pragma unroll 1
        for (int i = 0; i < 7; i++) {
            if (i == 0 && have_k1) {
                kb[0][0] = k1c0; kb[0][1] = k1c1; kb[0][2] = k1c2;
                continue;
            }
            float yi0 = y0, yi1 = y1, yi2 = y2;
            for (int j = 0; j < i; j++) {
                float c = dtc * cA[i][j];
                yi0 += c * kb[j][0];
                yi1 += c * kb[j][1];
                yi2 += c * kb[j][2];
            }
            float3 f = mlp_eval(sW1t, sb1, sW2, sb2, sW3, sb3,
                                t + cC[i] * dtc, yi0, yi1, yi2);
            kb[i][0] = f.x; kb[i][1] = f.y; kb[i][2] = f.z;
        }

        float yn0 = y0, yn1 = y1, yn2 = y2;
        float ye0 = 0.0f, ye1 = 0.0f, ye2 = 0.0f;
        for (int i = 0; i < 7; i++) {
            float cb = dtc * cB[i];
            float ce = dtc * cE[i];
            yn0 += cb * kb[i][0]; yn1 += cb * kb[i][1]; yn2 += cb * kb[i][2];
            ye0 += ce * kb[i][0]; ye1 += ce * kb[i][1]; ye2 += ce * kb[i][2];
        }

        // ---- per-thread error, warp shuffle reduce + cross-warp ----
        float local;
        {
            float tol0 = 1e-5f + 1e-5f * fmaxf(fabsf(y0), fabsf(yn0));
            float tol1 = 1e-5f + 1e-5f * fmaxf(fabsf(y1), fabsf(yn1));
            float tol2 = 1e-5f + 1e-5f * fmaxf(fabsf(y2), fabsf(yn2));
            float r0 = ye0 / tol0, r1 = ye1 / tol1, r2 = ye2 / tol2;
            local = r0*r0 + (r1*r1 + r2*r2);
        }
#pragma unroll
        for (int o = 16; o > 0; o >>= 1)
            local += __shfl_down_sync(0xFFFFFFFFu, local, o);
        if (lane == 0) rwarp[wid] = local;
        __syncthreads();

        // ---- grid barrier: publish block partial, arrive, spin ----
        const int buf = s & 1;
        if (tid == 0) {
            float bsum = rwarp[0];
#pragma unroll
            for (int w = 1; w < NWARP; w++) bsum += rwarp[w];
            g_partials[buf][bid] = bsum;
            __threadfence();
            atomicAdd((int*)&g_count[s], 1);
            while (g_count[s] < NBLK) { }
            __threadfence();
        }
        __syncthreads();

        // ---- redundant deterministic controller (all blocks identical) ----
        // warps 0..3 each reduce 32 of the 128 partials, then everyone sums
        // the 4 results in fixed order.
        if (wid < 4) {
            float v = g_partials[buf][wid * 32 + lane];
#pragma unroll
            for (int o = 16; o > 0; o >>= 1)
                v += __shfl_down_sync(0xFFFFFFFFu, v, o);
            if (lane == 0) rctrl[wid] = v;
        }
        __syncthreads();
        float total = ((rctrl[0] + rctrl[1]) + (rctrl[2] + rctrl[3]));
        __syncthreads();                           // rctrl reusable next iter

        float err = sqrtf(total / (float)NELEM);
        err = fmaxf(err, 1e-10f);
        bool accept = err <= 1.0f;
        float factor = 0.9f * powf(err, -0.2f);
        factor = fminf(fmaxf(factor, 0.2f), 10.0f);
        if (accept) {
            t += dtc; y0 = yn0; y1 = yn1; y2 = yn2;
            // FSAL: stage-7 input was bitwise y_new at time t+dtc -> next k1
            k1c0 = kb[6][0]; k1c1 = kb[6][1]; k1c2 = kb[6][2];
        } else {
            // (t, y) unchanged -> current k1 (stage 0) still valid
            k1c0 = kb[0][0]; k1c1 = kb[0][1]; k1c2 = kb[0][2];
        }
        have_k1 = true;
        dt = dtc * factor;
    }

    yout[3*n + 0] = y0;
    yout[3*n + 1] = y1;
    yout[3*n + 2] = y2;
}

// ---------------- launch --------------------------------------------------
extern "C" void kernel_launch(void* const* d_in, const int* in_sizes, int n_in,
                              void* d_out, int out_size)
{
    const float* y_in = (const float*)d_in[0];
    const float* W1   = (const float*)d_in[1];
    const float* b1   = (const float*)d_in[2];
    const float* W2   = (const float*)d_in[3];
    const float* b2   = (const float*)d_in[4];
    const float* W3   = (const float*)d_in[5];
    const float* b3   = (const float*)d_in[6];
    float* y = (float*)d_out;

    ode_init_kernel<<<1, 32>>>();
    ode_persistent_kernel<<<NBLK, TPB>>>(y_in, W1, b1, W2, b2, W3, b3, y);
}

// round 11
// speedup vs baseline: 2.0491x; 1.1463x over previous
#include <cuda_runtime.h>
#include <math.h>

#define N_PTS 32768
#define H     64
#define NBLK  128
#define TPB   256
#define NELEM (N_PTS*3)
#define MAX_STEPS 24
#define NWARP (TPB/32)

// ---------------- persistent device state (no allocation) ----------------
__device__ volatile int   g_count[MAX_STEPS];
__device__ volatile float g_partials[2][NBLK];

// ---------------- dopri5 tableau ------------------------------------------
__constant__ float cC[7] = { 0.0f, 0.2f, 0.3f, 0.8f, (float)(8.0/9.0), 1.0f, 1.0f };
__constant__ float cA[7][6] = {
    {0,0,0,0,0,0},
    {(float)(1.0/5.0),0,0,0,0,0},
    {(float)(3.0/40.0),(float)(9.0/40.0),0,0,0,0},
    {(float)(44.0/45.0),(float)(-56.0/15.0),(float)(32.0/9.0),0,0,0},
    {(float)(19372.0/6561.0),(float)(-25360.0/2187.0),(float)(64448.0/6561.0),(float)(-212.0/729.0),0,0},
    {(float)(9017.0/3168.0),(float)(-355.0/33.0),(float)(46732.0/5247.0),(float)(49.0/176.0),(float)(-5103.0/18656.0),0},
    {(float)(35.0/384.0),0.0f,(float)(500.0/1113.0),(float)(125.0/192.0),(float)(-2187.0/6784.0),(float)(11.0/84.0)},
};
__constant__ float cB[7] = {
    (float)(35.0/384.0), 0.0f, (float)(500.0/1113.0), (float)(125.0/192.0),
    (float)(-2187.0/6784.0), (float)(11.0/84.0), 0.0f
};
__constant__ float cE[7] = {
    (float)(35.0/384.0 - 5179.0/57600.0),
    0.0f,
    (float)(500.0/1113.0 - 7571.0/16695.0),
    (float)(125.0/192.0 - 393.0/640.0),
    (float)(-2187.0/6784.0 + 92097.0/339200.0),
    (float)(11.0/84.0 - 187.0/2100.0),
    (float)(-1.0/40.0)
};

// ---------------- packed f32x2 helpers (Blackwell FFMA2) ------------------
__device__ __forceinline__ unsigned long long ffma2(unsigned long long a,
                                                    unsigned long long b,
                                                    unsigned long long c)
{
    unsigned long long d;
    asm("fma.rn.f32x2 %0, %1, %2, %3;" : "=l"(d) : "l"(a), "l"(b), "l"(c));
    return d;
}
__device__ __forceinline__ unsigned long long splat2(float x)
{
    unsigned long long d;
    asm("mov.b64 %0, {%1, %1};" : "=l"(d) : "f"(x));
    return d;
}
__device__ __forceinline__ void unpack2(unsigned long long v, float& lo, float& hi)
{
    asm("mov.b64 {%0, %1}, %2;" : "=f"(lo), "=f"(hi) : "l"(v));
}

// ---------------- hardware tanh: single MUFU.TANH -------------------------
__device__ __forceinline__ float fast_tanh(float x)
{
    float y;
    asm("tanh.approx.f32 %0, %1;" : "=f"(y) : "f"(x));
    return y;
}

// ---------------- MLP: x(3)+t -> tanh(64) -> tanh(64) -> 3 ---------------
// Layer 1 fused into the layer-2 k-loop; 32 packed f32x2 accumulators.
__device__ __forceinline__ float3 mlp_eval(
    const float4* __restrict__ sW1t, const float* __restrict__ sb1,
    const float*  __restrict__ sW2,  const float* __restrict__ sb2,
    const float4* __restrict__ sW3,  const float* __restrict__ sb3,
    float t, float x0, float x1, float x2)
{
    unsigned long long acc[H / 2];          // 32 packed pairs = 64 neurons
    {
        const unsigned long long* b2p = (const unsigned long long*)sb2;
#pragma unroll
        for (int p = 0; p < H / 2; p++) acc[p] = b2p[p];
    }

#pragma unroll 8
    for (int k = 0; k < H; k++) {
        float4 w = sW1t[k];
        float a = fmaf(t, w.w, sb1[k]);
        a = fmaf(x2, w.z, a);
        a = fmaf(x1, w.y, a);
        a = fmaf(x0, w.x, a);
        unsigned long long hs = splat2(fast_tanh(a));

        const ulonglong2* wrow = (const ulonglong2*)(sW2 + k * H);
#pragma unroll
        for (int q = 0; q < H / 4; q++) {     // full 64-float row
            ulonglong2 wv = wrow[q];
            acc[2 * q]     = ffma2(hs, wv.x, acc[2 * q]);
            acc[2 * q + 1] = ffma2(hs, wv.y, acc[2 * q + 1]);
        }
    }

    float o0 = sb3[0], o1 = sb3[1], o2 = sb3[2];
#pragma unroll
    for (int p = 0; p < H / 2; p++) {
        float u, v;
        unpack2(acc[p], u, v);
        float ha = fast_tanh(u);
        float hb = fast_tanh(v);
        float4 wa = sW3[2 * p];
        float4 wb = sW3[2 * p + 1];
        o0 = fmaf(ha, wa.x, o0); o1 = fmaf(ha, wa.y, o1); o2 = fmaf(ha, wa.z, o2);
        o0 = fmaf(hb, wb.x, o0); o1 = fmaf(hb, wb.y, o1); o2 = fmaf(hb, wb.z, o2);
    }
    return make_float3(o0, o1, o2);
}

// ---------------- init: reset barrier counters every replay ---------------
__global__ void ode_init_kernel()
{
    int i = threadIdx.x;
    if (i < MAX_STEPS) g_count[i] = 0;
}

// ---------------- persistent fused integrator (FSAL) ----------------------
__global__ void __launch_bounds__(TPB, 1)
ode_persistent_kernel(const float* __restrict__ yin,
                      const float* __restrict__ W1, const float* __restrict__ b1,
                      const float* __restrict__ W2, const float* __restrict__ b2,
                      const float* __restrict__ W3, const float* __restrict__ b3,
                      float* __restrict__ yout)
{
    __shared__ __align__(16) float4 sW1t[H];
    __shared__ __align__(16) float  sb1[H];
    __shared__ __align__(16) float  sW2[H * H];    // natural [k][j] layout
    __shared__ __align__(16) float  sb2[H];
    __shared__ __align__(16) float4 sW3[H];
    __shared__ __align__(16) float  sb3[4];
    __shared__ float  rwarp[NWARP];                // per-warp partials
    __shared__ float  rctrl[4];                    // controller cross-warp partials

    const int tid  = threadIdx.x;
    const int bid  = blockIdx.x;
    const int lane = tid & 31;
    const int wid  = tid >> 5;

    {
        const float4* src = (const float4*)W2;
        float4* dst = (float4*)sW2;
        for (int idx = tid; idx < H * H / 4; idx += TPB) dst[idx] = src[idx];
    }
    if (tid < H) {
        sW1t[tid] = make_float4(W1[0*H + tid], W1[1*H + tid], W1[2*H + tid], W1[3*H + tid]);
        sb1[tid] = b1[tid];
        sb2[tid] = b2[tid];
        sW3[tid] = make_float4(W3[tid*3 + 0], W3[tid*3 + 1], W3[tid*3 + 2], 0.0f);
    }
    if (tid < 3) sb3[tid] = b3[tid];
    __syncthreads();

    const int n = bid * TPB + tid;
    float y0 = yin[3*n + 0];
    float y1 = yin[3*n + 1];
    float y2 = yin[3*n + 2];

    float t  = 0.0f;
    float dt = 0.05f;

    // FSAL cache: k1 at current (t, y). Valid after the first step.
    float k1c0 = 0.0f, k1c1 = 0.0f, k1c2 = 0.0f;
    bool  have_k1 = false;

    for (int s = 0; s < MAX_STEPS; s++) {
        const float rem = 1.0f - t;
        if (!(rem > 1e-9f)) break;                 // identical across blocks
        const float dtc = fminf(dt, rem);

        // ---- 7 dopri5 stages (stage 0 from FSAL cache when available) ----
        float kb[7][3];
#pragma unroll 1
        for (int i = 0; i < 7; i++) {
            if (i == 0 && have_k1) {
                kb[0][0] = k1c0; kb[0][1] = k1c1; kb[0][2] = k1c2;
                continue;
            }
            float yi0 = y0, yi1 = y1, yi2 = y2;
            for (int j = 0; j < i; j++) {
                float c = dtc * cA[i][j];
                yi0 += c * kb[j][0];
                yi1 += c * kb[j][1];
                yi2 += c * kb[j][2];
            }
            float3 f = mlp_eval(sW1t, sb1, sW2, sb2, sW3, sb3,
                                t + cC[i] * dtc, yi0, yi1, yi2);
            kb[i][0] = f.x; kb[i][1] = f.y; kb[i][2] = f.z;
        }

        float yn0 = y0, yn1 = y1, yn2 = y2;
        float ye0 = 0.0f, ye1 = 0.0f, ye2 = 0.0f;
        for (int i = 0; i < 7; i++) {
            float cb = dtc * cB[i];
            float ce = dtc * cE[i];
            yn0 += cb * kb[i][0]; yn1 += cb * kb[i][1]; yn2 += cb * kb[i][2];
            ye0 += ce * kb[i][0]; ye1 += ce * kb[i][1]; ye2 += ce * kb[i][2];
        }

        // ---- per-thread error, warp shuffle reduce + cross-warp ----
        float local;
        {
            float tol0 = 1e-5f + 1e-5f * fmaxf(fabsf(y0), fabsf(yn0));
            float tol1 = 1e-5f + 1e-5f * fmaxf(fabsf(y1), fabsf(yn1));
            float tol2 = 1e-5f + 1e-5f * fmaxf(fabsf(y2), fabsf(yn2));
            float r0 = ye0 / tol0, r1 = ye1 / tol1, r2 = ye2 / tol2;
            local = r0*r0 + (r1*r1 + r2*r2);
        }
#pragma unroll
        for (int o = 16; o > 0; o >>= 1)
            local += __shfl_down_sync(0xFFFFFFFFu, local, o);
        if (lane == 0) rwarp[wid] = local;
        __syncthreads();

        // ---- grid barrier: publish block partial, arrive, spin ----
        const int buf = s & 1;
        if (tid == 0) {
            float bsum = rwarp[0];
#pragma unroll
            for (int w = 1; w < NWARP; w++) bsum += rwarp[w];
            g_partials[buf][bid] = bsum;
            __threadfence();
            atomicAdd((int*)&g_count[s], 1);
            while (g_count[s] < NBLK) { }
            __threadfence();
        }
        __syncthreads();

        // ---- redundant deterministic controller (all blocks identical) ----
        if (wid < 4) {
            float v = g_partials[buf][wid * 32 + lane];
#pragma unroll
            for (int o = 16; o > 0; o >>= 1)
                v += __shfl_down_sync(0xFFFFFFFFu, v, o);
            if (lane == 0) rctrl[wid] = v;
        }
        __syncthreads();
        float total = ((rctrl[0] + rctrl[1]) + (rctrl[2] + rctrl[3]));
        __syncthreads();                           // rctrl reusable next iter

        float err = sqrtf(total / (float)NELEM);
        err = fmaxf(err, 1e-10f);
        bool accept = err <= 1.0f;
        float factor = 0.9f * powf(err, -0.2f);
        factor = fminf(fmaxf(factor, 0.2f), 10.0f);
        if (accept) {
            t += dtc; y0 = yn0; y1 = yn1; y2 = yn2;
            // FSAL: stage-7 input was bitwise y_new at time t+dtc -> next k1
            k1c0 = kb[6][0]; k1c1 = kb[6][1]; k1c2 = kb[6][2];
        } else {
            // (t, y) unchanged -> current k1 (stage 0) still valid
            k1c0 = kb[0][0]; k1c1 = kb[0][1]; k1c2 = kb[0][2];
        }
        have_k1 = true;
        dt = dtc * factor;
    }

    yout[3*n + 0] = y0;
    yout[3*n + 1] = y1;
    yout[3*n + 2] = y2;
}

// ---------------- launch --------------------------------------------------
extern "C" void kernel_launch(void* const* d_in, const int* in_sizes, int n_in,
                              void* d_out, int out_size)
{
    const float* y_in = (const float*)d_in[0];
    const float* W1   = (const float*)d_in[1];
    const float* b1   = (const float*)d_in[2];
    const float* W2   = (const float*)d_in[3];
    const float* b2   = (const float*)d_in[4];
    const float* W3   = (const float*)d_in[5];
    const float* b3   = (const float*)d_in[6];
    float* y = (float*)d_out;

    ode_init_kernel<<<1, 32>>>();
    ode_persistent_kernel<<<NBLK, TPB>>>(y_in, W1, b1, W2, b2, W3, b3, y);
}

// round 12
// speedup vs baseline: 2.5265x; 1.2330x over previous
#include <cuda_runtime.h>
#include <math.h>

#define N_PTS 32768
#define H     64
#define NBLK  128
#define TPB   128          // 4 warps; each thread owns 2 points
#define PTS_PER_BLK 256
#define NELEM (N_PTS*3)
#define MAX_STEPS 24
#define NWARP (TPB/32)

// ---------------- persistent device state (no allocation) ----------------
__device__ volatile int   g_count[MAX_STEPS];
__device__ volatile float g_partials[2][NBLK];

// ---------------- dopri5 tableau ------------------------------------------
__constant__ float cC[7] = { 0.0f, 0.2f, 0.3f, 0.8f, (float)(8.0/9.0), 1.0f, 1.0f };
__constant__ float cA[7][6] = {
    {0,0,0,0,0,0},
    {(float)(1.0/5.0),0,0,0,0,0},
    {(float)(3.0/40.0),(float)(9.0/40.0),0,0,0,0},
    {(float)(44.0/45.0),(float)(-56.0/15.0),(float)(32.0/9.0),0,0,0},
    {(float)(19372.0/6561.0),(float)(-25360.0/2187.0),(float)(64448.0/6561.0),(float)(-212.0/729.0),0,0},
    {(float)(9017.0/3168.0),(float)(-355.0/33.0),(float)(46732.0/5247.0),(float)(49.0/176.0),(float)(-5103.0/18656.0),0},
    {(float)(35.0/384.0),0.0f,(float)(500.0/1113.0),(float)(125.0/192.0),(float)(-2187.0/6784.0),(float)(11.0/84.0)},
};
__constant__ float cB[7] = {
    (float)(35.0/384.0), 0.0f, (float)(500.0/1113.0), (float)(125.0/192.0),
    (float)(-2187.0/6784.0), (float)(11.0/84.0), 0.0f
};
__constant__ float cE[7] = {
    (float)(35.0/384.0 - 5179.0/57600.0),
    0.0f,
    (float)(500.0/1113.0 - 7571.0/16695.0),
    (float)(125.0/192.0 - 393.0/640.0),
    (float)(-2187.0/6784.0 + 92097.0/339200.0),
    (float)(11.0/84.0 - 187.0/2100.0),
    (float)(-1.0/40.0)
};

// ---------------- packed f32x2 helpers (Blackwell FFMA2) ------------------
__device__ __forceinline__ unsigned long long ffma2(unsigned long long a,
                                                    unsigned long long b,
                                                    unsigned long long c)
{
    unsigned long long d;
    asm("fma.rn.f32x2 %0, %1, %2, %3;" : "=l"(d) : "l"(a), "l"(b), "l"(c));
    return d;
}
__device__ __forceinline__ unsigned long long splat2(float x)
{
    unsigned long long d;
    asm("mov.b64 %0, {%1, %1};" : "=l"(d) : "f"(x));
    return d;
}
__device__ __forceinline__ void unpack2(unsigned long long v, float& lo, float& hi)
{
    asm("mov.b64 {%0, %1}, %2;" : "=f"(lo), "=f"(hi) : "l"(v));
}

// ---------------- hardware tanh: single MUFU.TANH -------------------------
__device__ __forceinline__ float fast_tanh(float x)
{
    float y;
    asm("tanh.approx.f32 %0, %1;" : "=f"(y) : "f"(x));
    return y;
}

// ---------------- dual-point MLP eval --------------------------------------
// Two points share every weight load. Output-neuron dim processed in two
// halves of 32 (16 packed accs per point) to bound register pressure;
// layer-1 activations are recomputed per half (cheap pipes, no registers).
__device__ __forceinline__ void mlp_eval2(
    const float4* __restrict__ sW1t, const float* __restrict__ sb1,
    const float*  __restrict__ sW2,  const float* __restrict__ sb2,
    const float4* __restrict__ sW3,  const float* __restrict__ sb3,
    float t,
    float xA0, float xA1, float xA2,
    float xB0, float xB1, float xB2,
    float3& fA, float3& fB)
{
    float oA0 = sb3[0], oA1 = sb3[1], oA2 = sb3[2];
    float oB0 = sb3[0], oB1 = sb3[1], oB2 = sb3[2];

#pragma unroll 1
    for (int jh = 0; jh < 2; jh++) {
        const int nb = jh * (H / 2);
        unsigned long long accA[H / 4], accB[H / 4];   // 16 pairs = 32 neurons
        {
            const unsigned long long* b2p = (const unsigned long long*)(sb2 + nb);
#pragma unroll
            for (int p = 0; p < H / 4; p++) { accA[p] = b2p[p]; accB[p] = b2p[p]; }
        }

#pragma unroll 4
        for (int k = 0; k < H; k++) {
            float4 w = sW1t[k];                        // shared (broadcast)
            float b = sb1[k];
            float aA = fmaf(t, w.w, b);
            aA = fmaf(xA2, w.z, aA);
            aA = fmaf(xA1, w.y, aA);
            aA = fmaf(xA0, w.x, aA);
            float aB = fmaf(t, w.w, b);
            aB = fmaf(xB2, w.z, aB);
            aB = fmaf(xB1, w.y, aB);
            aB = fmaf(xB0, w.x, aB);
            unsigned long long hsA = splat2(fast_tanh(aA));
            unsigned long long hsB = splat2(fast_tanh(aB));

            const ulonglong2* wrow = (const ulonglong2*)(sW2 + k * H + nb);
#pragma unroll
            for (int q = 0; q < H / 8; q++) {          // 8 x 16B = 32 floats
                ulonglong2 wv = wrow[q];               // shared (broadcast)
                accA[2 * q]     = ffma2(hsA, wv.x, accA[2 * q]);
                accA[2 * q + 1] = ffma2(hsA, wv.y, accA[2 * q + 1]);
                accB[2 * q]     = ffma2(hsB, wv.x, accB[2 * q]);
                accB[2 * q + 1] = ffma2(hsB, wv.y, accB[2 * q + 1]);
            }
        }

#pragma unroll
        for (int p = 0; p < H / 4; p++) {
            float4 wa = sW3[nb + 2 * p];               // shared
            float4 wb = sW3[nb + 2 * p + 1];
            float u, v;
            unpack2(accA[p], u, v);
            float ha = fast_tanh(u), hb = fast_tanh(v);
            oA0 = fmaf(ha, wa.x, oA0); oA1 = fmaf(ha, wa.y, oA1); oA2 = fmaf(ha, wa.z, oA2);
            oA0 = fmaf(hb, wb.x, oA0); oA1 = fmaf(hb, wb.y, oA1); oA2 = fmaf(hb, wb.z, oA2);
            unpack2(accB[p], u, v);
            ha = fast_tanh(u); hb = fast_tanh(v);
            oB0 = fmaf(ha, wa.x, oB0); oB1 = fmaf(ha, wa.y, oB1); oB2 = fmaf(ha, wa.z, oB2);
            oB0 = fmaf(hb, wb.x, oB0); oB1 = fmaf(hb, wb.y, oB1); oB2 = fmaf(hb, wb.z, oB2);
        }
    }
    fA = make_float3(oA0, oA1, oA2);
    fB = make_float3(oB0, oB1, oB2);
}

// ---------------- init: reset barrier counters every replay ---------------
__global__ void ode_init_kernel()
{
    int i = threadIdx.x;
    if (i < MAX_STEPS) g_count[i] = 0;
}

// ---------------- persistent fused integrator (FSAL, 2 pts/thread) --------
__global__ void __launch_bounds__(TPB, 1)
ode_persistent_kernel(const float* __restrict__ yin,
                      const float* __restrict__ W1, const float* __restrict__ b1,
                      const float* __restrict__ W2, const float* __restrict__ b2,
                      const float* __restrict__ W3, const float* __restrict__ b3,
                      float* __restrict__ yout)
{
    __shared__ __align__(16) float4 sW1t[H];
    __shared__ __align__(16) float  sb1[H];
    __shared__ __align__(16) float  sW2[H * H];    // natural [k][j] layout
    __shared__ __align__(16) float  sb2[H];
    __shared__ __align__(16) float4 sW3[H];
    __shared__ __align__(16) float  sb3[4];
    __shared__ float  rwarp[NWARP];
    __shared__ float  rctrl[4];

    const int tid  = threadIdx.x;
    const int bid  = blockIdx.x;
    const int lane = tid & 31;
    const int wid  = tid >> 5;

    {
        const float4* src = (const float4*)W2;
        float4* dst = (float4*)sW2;
        for (int idx = tid; idx < H * H / 4; idx += TPB) dst[idx] = src[idx];
    }
    if (tid < H) {
        sW1t[tid] = make_float4(W1[0*H + tid], W1[1*H + tid], W1[2*H + tid], W1[3*H + tid]);
        sb1[tid] = b1[tid];
        sb2[tid] = b2[tid];
        sW3[tid] = make_float4(W3[tid*3 + 0], W3[tid*3 + 1], W3[tid*3 + 2], 0.0f);
    }
    if (tid < 3) sb3[tid] = b3[tid];
    __syncthreads();

    const int nA = bid * PTS_PER_BLK + tid;
    const int nB = nA + TPB;

    float yA0 = yin[3*nA + 0], yA1 = yin[3*nA + 1], yA2 = yin[3*nA + 2];
    float yB0 = yin[3*nB + 0], yB1 = yin[3*nB + 1], yB2 = yin[3*nB + 2];

    float t  = 0.0f;
    float dt = 0.05f;

    // FSAL caches for both points
    float kA0 = 0.0f, kA1 = 0.0f, kA2 = 0.0f;
    float kB0 = 0.0f, kB1 = 0.0f, kB2 = 0.0f;
    bool  have_k1 = false;

    for (int s = 0; s < MAX_STEPS; s++) {
        const float rem = 1.0f - t;
        if (!(rem > 1e-9f)) break;                 // identical across blocks
        const float dtc = fminf(dt, rem);

        float kbA[7][3], kbB[7][3];
#pragma unroll 1
        for (int i = 0; i < 7; i++) {
            if (i == 0 && have_k1) {
                kbA[0][0] = kA0; kbA[0][1] = kA1; kbA[0][2] = kA2;
                kbB[0][0] = kB0; kbB[0][1] = kB1; kbB[0][2] = kB2;
                continue;
            }
            float yiA0 = yA0, yiA1 = yA1, yiA2 = yA2;
            float yiB0 = yB0, yiB1 = yB1, yiB2 = yB2;
            for (int j = 0; j < i; j++) {
                float c = dtc * cA[i][j];
                yiA0 += c * kbA[j][0]; yiA1 += c * kbA[j][1]; yiA2 += c * kbA[j][2];
                yiB0 += c * kbB[j][0]; yiB1 += c * kbB[j][1]; yiB2 += c * kbB[j][2];
            }
            float3 fA, fB;
            mlp_eval2(sW1t, sb1, sW2, sb2, sW3, sb3, t + cC[i] * dtc,
                      yiA0, yiA1, yiA2, yiB0, yiB1, yiB2, fA, fB);
            kbA[i][0] = fA.x; kbA[i][1] = fA.y; kbA[i][2] = fA.z;
            kbB[i][0] = fB.x; kbB[i][1] = fB.y; kbB[i][2] = fB.z;
        }

        float ynA0 = yA0, ynA1 = yA1, ynA2 = yA2;
        float ynB0 = yB0, ynB1 = yB1, ynB2 = yB2;
        float yeA0 = 0.0f, yeA1 = 0.0f, yeA2 = 0.0f;
        float yeB0 = 0.0f, yeB1 = 0.0f, yeB2 = 0.0f;
        for (int i = 0; i < 7; i++) {
            float cb = dtc * cB[i];
            float ce = dtc * cE[i];
            ynA0 += cb * kbA[i][0]; ynA1 += cb * kbA[i][1]; ynA2 += cb * kbA[i][2];
            ynB0 += cb * kbB[i][0]; ynB1 += cb * kbB[i][1]; ynB2 += cb * kbB[i][2];
            yeA0 += ce * kbA[i][0]; yeA1 += ce * kbA[i][1]; yeA2 += ce * kbA[i][2];
            yeB0 += ce * kbB[i][0]; yeB1 += ce * kbB[i][1]; yeB2 += ce * kbB[i][2];
        }

        // ---- per-thread error (both points), warp reduce + cross-warp ----
        float local;
        {
            float tolA0 = 1e-5f + 1e-5f * fmaxf(fabsf(yA0), fabsf(ynA0));
            float tolA1 = 1e-5f + 1e-5f * fmaxf(fabsf(yA1), fabsf(ynA1));
            float tolA2 = 1e-5f + 1e-5f * fmaxf(fabsf(yA2), fabsf(ynA2));
            float tolB0 = 1e-5f + 1e-5f * fmaxf(fabsf(yB0), fabsf(ynB0));
            float tolB1 = 1e-5f + 1e-5f * fmaxf(fabsf(yB1), fabsf(ynB1));
            float tolB2 = 1e-5f + 1e-5f * fmaxf(fabsf(yB2), fabsf(ynB2));
            float rA0 = yeA0 / tolA0, rA1 = yeA1 / tolA1, rA2 = yeA2 / tolA2;
            float rB0 = yeB0 / tolB0, rB1 = yeB1 / tolB1, rB2 = yeB2 / tolB2;
            local = (rA0*rA0 + (rA1*rA1 + rA2*rA2))
                  + (rB0*rB0 + (rB1*rB1 + rB2*rB2));
        }
#pragma unroll
        for (int o = 16; o > 0; o >>= 1)
            local += __shfl_down_sync(0xFFFFFFFFu, local, o);
        if (lane == 0) rwarp[wid] = local;
        __syncthreads();

        // ---- grid barrier ----
        const int buf = s & 1;
        if (tid == 0) {
            float bsum = rwarp[0];
#pragma unroll
            for (int w = 1; w < NWARP; w++) bsum += rwarp[w];
            g_partials[buf][bid] = bsum;
            __threadfence();
            atomicAdd((int*)&g_count[s], 1);
            while (g_count[s] < NBLK) { }
            __threadfence();
        }
        __syncthreads();

        // ---- redundant deterministic controller ----
        if (wid < 4) {
            float v = g_partials[buf][wid * 32 + lane];
#pragma unroll
            for (int o = 16; o > 0; o >>= 1)
                v += __shfl_down_sync(0xFFFFFFFFu, v, o);
            if (lane == 0) rctrl[wid] = v;
        }
        __syncthreads();
        float total = ((rctrl[0] + rctrl[1]) + (rctrl[2] + rctrl[3]));
        __syncthreads();

        float err = sqrtf(total / (float)NELEM);
        err = fmaxf(err, 1e-10f);
        bool accept = err <= 1.0f;
        float factor = 0.9f * powf(err, -0.2f);
        factor = fminf(fmaxf(factor, 0.2f), 10.0f);
        if (accept) {
            t += dtc;
            yA0 = ynA0; yA1 = ynA1; yA2 = ynA2;
            yB0 = ynB0; yB1 = ynB1; yB2 = ynB2;
            kA0 = kbA[6][0]; kA1 = kbA[6][1]; kA2 = kbA[6][2];
            kB0 = kbB[6][0]; kB1 = kbB[6][1]; kB2 = kbB[6][2];
        } else {
            kA0 = kbA[0][0]; kA1 = kbA[0][1]; kA2 = kbA[0][2];
            kB0 = kbB[0][0]; kB1 = kbB[0][1]; kB2 = kbB[0][2];
        }
        have_k1 = true;
        dt = dtc * factor;
    }

    yout[3*nA + 0] = yA0; yout[3*nA + 1] = yA1; yout[3*nA + 2] = yA2;
    yout[3*nB + 0] = yB0; yout[3*nB + 1] = yB1; yout[3*nB + 2] = yB2;
}

// ---------------- launch --------------------------------------------------
extern "C" void kernel_launch(void* const* d_in, const int* in_sizes, int n_in,
                              void* d_out, int out_size)
{
    const float* y_in = (const float*)d_in[0];
    const float* W1   = (const float*)d_in[1];
    const float* b1   = (const float*)d_in[2];
    const float* W2   = (const float*)d_in[3];
    const float* b2   = (const float*)d_in[4];
    const float* W3   = (const float*)d_in[5];
    const float* b3   = (const float*)d_in[6];
    float* y = (float*)d_out;

    ode_init_kernel<<<1, 32>>>();
    ode_persistent_kernel<<<NBLK, TPB>>>(y_in, W1, b1, W2, b2, W3, b3, y);
}